// round 15
// baseline (speedup 1.0000x reference)
#include <cuda_runtime.h>
#include <cuda_fp16.h>
#include <cstdint>

// Cosine self-attention, fp16 mma.sync m16n8k16.
// R14: lane-major fragment images improved gemm2 (182us, tensor 63%) but
// producers' scattered 4B gmem stores regressed the total.
// R15: keep R14 mainloops verbatim; producers (xhat, gemm1 epilogue) now
// scatter into SMEM stagings and write gmem fully coalesced.

#define BATCH 16
#define SEQ   2048
#define DIM   512
#define NTILE 16
#define NPAIR 136
#define TILE_U32 2048                 // 128 rows x 32 halves = 8KB
#define TILE_B   8192
#define STAGE_U32 8192                // 2 A-tiles + 2 B-tiles
#define STAGE_B   32768
#define SMEM_DYN  98304               // 3 stages

__device__ __align__(256) uint32_t g_xhA[(size_t)BATCH * 16 * 16 * TILE_U32];
__device__ __align__(256) uint32_t g_xhB[(size_t)BATCH * 16 * 16 * TILE_U32];
__device__ __align__(256) uint32_t g_xT[(size_t)BATCH * 4 * 64 * TILE_U32];
__device__ __align__(256) uint32_t g_P[(size_t)BATCH * 16 * 64 * TILE_U32];

// ---------------- ptx helpers ----------------
__device__ __forceinline__ void mma16(float c[4], const uint32_t a[4],
                                      const uint32_t b[2]) {
    asm volatile(
        "mma.sync.aligned.m16n8k16.row.col.f32.f16.f16.f32 "
        "{%0,%1,%2,%3}, {%4,%5,%6,%7}, {%8,%9}, {%0,%1,%2,%3};"
        : "+f"(c[0]), "+f"(c[1]), "+f"(c[2]), "+f"(c[3])
        : "r"(a[0]), "r"(a[1]), "r"(a[2]), "r"(a[3]), "r"(b[0]), "r"(b[1]));
}
__device__ __forceinline__ uint32_t movmat(uint32_t a) {
    uint32_t d;
    asm("movmatrix.sync.aligned.m8n8.trans.b16 %0, %1;" : "=r"(d) : "r"(a));
    return d;
}
__device__ __forceinline__ void mbar_init(uint32_t mbar, uint32_t cnt) {
    asm volatile("mbarrier.init.shared.b64 [%0], %1;" :: "r"(mbar), "r"(cnt)
                 : "memory");
}
__device__ __forceinline__ void mbar_expect(uint32_t mbar, uint32_t bytes) {
    asm volatile("mbarrier.arrive.expect_tx.shared.b64 _, [%0], %1;"
                 :: "r"(mbar), "r"(bytes) : "memory");
}
__device__ __forceinline__ void mbar_wait(uint32_t mbar, uint32_t parity) {
    asm volatile(
        "{\n\t.reg .pred P1;\n\t"
        "WL_%=:\n\t"
        "mbarrier.try_wait.parity.acquire.cta.shared::cta.b64 P1, [%0], %1, 0x989680;\n\t"
        "@P1 bra.uni WD_%=;\n\t"
        "bra.uni WL_%=;\n\t"
        "WD_%=:\n\t}"
        :: "r"(mbar), "r"(parity) : "memory");
}
__device__ __forceinline__ void bulk_cp(uint32_t dst, const void* src,
                                        uint32_t bytes, uint32_t mbar) {
    asm volatile(
        "cp.async.bulk.shared::cluster.global.mbarrier::complete_tx::bytes "
        "[%0], [%1], %2, [%3];"
        :: "r"(dst), "l"(src), "r"(bytes), "r"(mbar) : "memory");
}
__device__ __forceinline__ void fence_async() {
    asm volatile("fence.proxy.async.shared::cta;" ::: "memory");
}

// ---------- lane-major fragment-image index helpers ----------
// A image u32 idx (row r, k-pair u = k>>1; ks=u>>3, kp8=u&7):
//   ((ks*8 + (r>>4))*32 + (r&7)*4 + (kp8&3))*4 + (kp8>>2)*2 + ((r>>3)&1)
// B image u32 idx (col n, u):
//   ((ks*16 + (n>>3))*32 + (n&7)*4 + (kp8&3))*2 + (kp8>>2)
__device__ __forceinline__ int a_img(int r, int u) {
    const int ks = u >> 3, kp = u & 7;
    return (((ks * 8 + (r >> 4)) * 32) + (r & 7) * 4 + (kp & 3)) * 4 +
           (kp >> 2) * 2 + ((r >> 3) & 1);
}
__device__ __forceinline__ int b_img(int n, int u) {
    const int ks = u >> 3, kp = u & 7;
    return (((ks * 16 + (n >> 3)) * 32) + (n & 7) * 4 + (kp & 3)) * 2 + (kp >> 2);
}

// ------- kernel: xhat -> A-image + B-image tiles (smem-staged, coalesced) --
// One CTA per (batch, 128-row block). Phase 1: norms. Phase 2: per kc chunk,
// scatter into smem tile images, copy out coalesced.
__global__ __launch_bounds__(256) void xhat_kernel(const float* __restrict__ x) {
    __shared__ uint32_t sA[TILE_U32];
    __shared__ uint32_t sB[TILE_U32];
    __shared__ float snorm[128];
    const int blk = blockIdx.x;            // b*16 + rb
    const int b = blk >> 4, rb = blk & 15;
    const int tid = threadIdx.x, wid = tid >> 5, lane = tid & 31;
    const float* xb = x + ((size_t)(b * 16 + rb) * 128) * DIM;

    // phase 1: warp-per-row norms (16 passes x 8 warps)
    for (int p = 0; p < 16; p++) {
        const int row = p * 8 + wid;
        const float4* xr = (const float4*)(xb + (size_t)row * DIM);
        float ss = 0.f;
#pragma unroll
        for (int i = 0; i < 4; i++) {
            float4 v = xr[i * 32 + lane];
            ss += v.x * v.x + v.y * v.y + v.z * v.z + v.w * v.w;
        }
#pragma unroll
        for (int m = 16; m; m >>= 1) ss += __shfl_xor_sync(0xffffffffu, ss, m);
        if (lane == 0) snorm[row] = 1.0f / sqrtf(ss);
    }
    __syncthreads();

    // phase 2: per kc chunk, stage and flush
    for (int kc = 0; kc < 16; kc++) {
#pragma unroll
        for (int i = 0; i < 4; i++) {
            const int j = tid * 4 + i;       // float4 id 0..1023
            const int rr = j >> 3, c4 = j & 7;
            const float s = snorm[rr];
            float4 w = ((const float4*)(xb + (size_t)rr * DIM + kc * 32))[c4];
            __half2 h0 = __floats2half2_rn(w.x * s, w.y * s);
            __half2 h1 = __floats2half2_rn(w.z * s, w.w * s);
            const int u0 = c4 * 2, u1 = c4 * 2 + 1;
            sA[a_img(rr, u0)] = *(uint32_t*)&h0;
            sA[a_img(rr, u1)] = *(uint32_t*)&h1;
            sB[b_img(rr, u0)] = *(uint32_t*)&h0;
            sB[b_img(rr, u1)] = *(uint32_t*)&h1;
        }
        __syncthreads();
        uint4* dA = (uint4*)(g_xhA + ((size_t)(blk * 16 + kc)) * TILE_U32);
        uint4* dB = (uint4*)(g_xhB + ((size_t)(blk * 16 + kc)) * TILE_U32);
#pragma unroll
        for (int i = 0; i < 2; i++) {
            dA[tid + i * 256] = ((const uint4*)sA)[tid + i * 256];
            dB[tid + i * 256] = ((const uint4*)sB)[tid + i * 256];
        }
        __syncthreads();
    }
}

// ---------------- kernel: xT -> B-image tiles ------------------------------
__global__ void xT_kernel(const float* __restrict__ x) {
    __shared__ float t[32][33];
    const int b = blockIdx.z, s0 = blockIdx.x * 32, d0 = blockIdx.y * 32;
    const int tx = threadIdx.x, ty = threadIdx.y;
#pragma unroll
    for (int i = 0; i < 4; i++)
        t[ty + 8 * i][tx] = x[((size_t)b * SEQ + s0 + ty + 8 * i) * DIM + d0 + tx];
    __syncthreads();
    const int kc = s0 >> 5;
    const int nb = d0 >> 7;
    const int n  = (d0 & 127) + tx;
    uint32_t* tile = g_xT + ((size_t)((b * 4 + nb) * 64 + kc)) * TILE_U32;
#pragma unroll
    for (int i = 0; i < 2; i++) {
        const int u = ty + 8 * i;
        __half2 hv = __floats2half2_rn(t[2 * u][tx], t[2 * u + 1][tx]);
        tile[b_img(n, u)] = *(uint32_t*)&hv;
    }
}

// ------------- GEMM core: bulk-fill pipeline + vector fragment loads -------
template <bool SUMROWS>
__device__ __forceinline__ void compute_chunk(const uint32_t* Abuf,
                                              const uint32_t* Bbuf,
                                              float c[4][4][4], int wm, int wn,
                                              int lane, float* sumA) {
#pragma unroll
    for (int ks = 0; ks < 2; ks++) {
        uint32_t a[4][4], b[4][2];
#pragma unroll
        for (int mt = 0; mt < 4; mt++) {
            uint4 v = *((const uint4*)Abuf + ((ks * 8 + wm * 4 + mt) * 32 + lane));
            a[mt][0] = v.x; a[mt][1] = v.y; a[mt][2] = v.z; a[mt][3] = v.w;
        }
#pragma unroll
        for (int nt = 0; nt < 4; nt++) {
            uint2 v = *((const uint2*)Bbuf + ((ks * 16 + wn * 4 + nt) * 32 + lane));
            b[nt][0] = v.x; b[nt][1] = v.y;
        }
        if (SUMROWS && wn == 0) {
#pragma unroll
            for (int mt = 0; mt < 4; mt++) {
                float2 f0 = __half22float2(*(__half2*)&a[mt][0]);
                float2 f2 = __half22float2(*(__half2*)&a[mt][2]);
                sumA[mt * 2] += (f0.x + f0.y) + (f2.x + f2.y);
                float2 f1 = __half22float2(*(__half2*)&a[mt][1]);
                float2 f3 = __half22float2(*(__half2*)&a[mt][3]);
                sumA[mt * 2 + 1] += (f1.x + f1.y) + (f3.x + f3.y);
            }
        }
#pragma unroll
        for (int mt = 0; mt < 4; mt++)
#pragma unroll
            for (int nt = 0; nt < 4; nt++)
                mma16(c[mt][nt], a[mt], b[nt]);
    }
}

// Chunk = 64 K-halves = 2 consecutive 8KB tiles per operand.
template <bool SUMROWS>
__device__ __forceinline__ void gemm_main(const char* Abase, const char* Bbase,
                                          int T, float c[4][4][4],
                                          uint32_t* smem, uint32_t smem_u32,
                                          uint32_t mbar_u32, int tid, int wm,
                                          int wn, int lane, float* sumA) {
    uint32_t ph0 = 0, ph1 = 0, ph2 = 0;
    auto issue = [&](int t) {
        if (tid == 0) {
            const int s = t % 3;
            const uint32_t mb = mbar_u32 + s * 8;
            mbar_expect(mb, STAGE_B);
            bulk_cp(smem_u32 + s * STAGE_B, Abase + (size_t)t * 2 * TILE_B,
                    2 * TILE_B, mb);
            bulk_cp(smem_u32 + s * STAGE_B + 2 * TILE_B,
                    Bbase + (size_t)t * 2 * TILE_B, 2 * TILE_B, mb);
        }
    };
    issue(0);
    if (T > 1) issue(1);
    for (int t = 0; t < T; t++) {
        const int s = t % 3;
        const uint32_t mb = mbar_u32 + s * 8;
        if (s == 0)      { mbar_wait(mb, ph0); ph0 ^= 1; }
        else if (s == 1) { mbar_wait(mb, ph1); ph1 ^= 1; }
        else             { mbar_wait(mb, ph2); ph2 ^= 1; }
        __syncthreads();
        if (t + 2 < T) issue(t + 2);
#pragma unroll
        for (int u = 0; u < 2; u++)
            compute_chunk<SUMROWS>(smem + s * STAGE_U32 + u * TILE_U32,
                                   smem + s * STAGE_U32 + 2 * TILE_U32 +
                                       u * TILE_U32,
                                   c, wm, wn, lane, sumA);
    }
}

// ------- kernel: GEMM1 (symmetric)  P = half(exp(xhat xhat^T - 1)) ---------
__global__ __launch_bounds__(256, 2) void gemm1_kernel() {
    extern __shared__ __align__(128) uint32_t smem[];
    __shared__ __align__(8) unsigned long long mbars[3];
    const uint32_t smem_u32 = (uint32_t)__cvta_generic_to_shared(smem);
    const uint32_t mbar_u32 = (uint32_t)__cvta_generic_to_shared(mbars);
    const int b = blockIdx.z;
    const int idx = blockIdx.x;
    int ti = (int)(NTILE + 0.5f -
                   sqrtf((NTILE + 0.5f) * (NTILE + 0.5f) - 2.0f * idx - 0.25f));
    while (ti * NTILE - ti * (ti - 1) / 2 > idx) ti--;
    while ((ti + 1) * NTILE - (ti + 1) * ti / 2 <= idx) ti++;
    const int tj = ti + (idx - (ti * NTILE - ti * (ti - 1) / 2));

    const int tid = threadIdx.x, wid = tid >> 5, lane = tid & 31;
    const int wm = wid >> 2, wn = wid & 3;

    if (tid == 0) {
#pragma unroll
        for (int s = 0; s < 3; s++) mbar_init(mbar_u32 + s * 8, 1);
        fence_async();
    }
    __syncthreads();

    const char* Abase =
        (const char*)(g_xhA + ((size_t)((b * 16 + ti) * 16)) * TILE_U32);
    const char* Bbase =
        (const char*)(g_xhB + ((size_t)((b * 16 + tj) * 16)) * TILE_U32);

    float c[4][4][4];
#pragma unroll
    for (int i = 0; i < 4; i++)
#pragma unroll
        for (int j = 0; j < 4; j++)
#pragma unroll
            for (int k = 0; k < 4; k++) c[i][j][k] = 0.f;
    float dummy[8];

    gemm_main<false>(Abase, Bbase, DIM / 64, c, smem, smem_u32, mbar_u32, tid,
                     wm, wn, lane, dummy);

    // --- epilogue: stage direct + mirror images in smem, flush coalesced ---
    const bool mirror = (ti != tj);
    __syncthreads();                    // pipeline smem now dead
    uint32_t* sD = smem;                // 8192 u32 = 4 tiles (q = wn)
    uint32_t* sM = smem + 8192;         // 8192 u32 = 4 tiles (q = wm*2+(mt>>1))
#pragma unroll
    for (int mt = 0; mt < 4; mt++) {
#pragma unroll
        for (int nt = 0; nt < 4; nt++) {
            __half2 h0 = __floats2half2_rn(__expf(c[mt][nt][0] - 1.0f),
                                           __expf(c[mt][nt][1] - 1.0f));
            __half2 h1 = __floats2half2_rn(__expf(c[mt][nt][2] - 1.0f),
                                           __expf(c[mt][nt][3] - 1.0f));
            const int ia = wn * TILE_U32 +
                           (((nt >> 1) * 8 + wm * 4 + mt) * 32 + lane) * 4 +
                           (nt & 1) * 2;
            sD[ia]     = *(uint32_t*)&h0;
            sD[ia + 1] = *(uint32_t*)&h1;
            if (mirror) {
                uint32_t t0 = movmat(*(uint32_t*)&h0);
                uint32_t t1 = movmat(*(uint32_t*)&h1);
                const int im = (wm * 2 + (mt >> 1)) * TILE_U32 +
                               (((mt & 1) * 8 + wn * 2 + (nt >> 1)) * 32 + lane)
                                   * 4 + (nt & 1);
                sM[im]     = t0;
                sM[im + 2] = t1;
            }
        }
    }
    __syncthreads();
    uint4* dD = (uint4*)(g_P + ((size_t)((b * 16 + ti) * 64 + tj * 4)) * TILE_U32);
#pragma unroll
    for (int i = 0; i < 8; i++)
        dD[tid + i * 256] = ((const uint4*)sD)[tid + i * 256];
    if (mirror) {
        uint4* dM =
            (uint4*)(g_P + ((size_t)((b * 16 + tj) * 64 + ti * 4)) * TILE_U32);
#pragma unroll
        for (int i = 0; i < 8; i++)
            dM[tid + i * 256] = ((const uint4*)sM)[tid + i * 256];
    }
}

// ------- kernel: GEMM2  out = (P @ x) / rowsum(P) --------------------------
__global__ __launch_bounds__(256, 2) void gemm2_kernel(float* __restrict__ out) {
    extern __shared__ __align__(128) uint32_t smem[];
    __shared__ __align__(8) unsigned long long mbars[3];
    const uint32_t smem_u32 = (uint32_t)__cvta_generic_to_shared(smem);
    const uint32_t mbar_u32 = (uint32_t)__cvta_generic_to_shared(mbars);
    const int b = blockIdx.z, mb = blockIdx.y, nb = blockIdx.x;
    const int tid = threadIdx.x, wid = tid >> 5, lane = tid & 31;
    const int wm = wid >> 2, wn = wid & 3;

    if (tid == 0) {
#pragma unroll
        for (int s = 0; s < 3; s++) mbar_init(mbar_u32 + s * 8, 1);
        fence_async();
    }
    __syncthreads();

    const char* Abase =
        (const char*)(g_P + ((size_t)((b * 16 + mb) * 64)) * TILE_U32);
    const char* Bbase =
        (const char*)(g_xT + ((size_t)((b * 4 + nb) * 64)) * TILE_U32);

    float c[4][4][4];
#pragma unroll
    for (int i = 0; i < 4; i++)
#pragma unroll
        for (int j = 0; j < 4; j++)
#pragma unroll
            for (int k = 0; k < 4; k++) c[i][j][k] = 0.f;
    float sumA[8];
#pragma unroll
    for (int i = 0; i < 8; i++) sumA[i] = 0.f;

    gemm_main<true>(Abase, Bbase, SEQ / 64, c, smem, smem_u32, mbar_u32, tid,
                    wm, wn, lane, sumA);

#pragma unroll
    for (int i = 0; i < 8; i++) {
        sumA[i] += __shfl_xor_sync(0xffffffffu, sumA[i], 1);
        sumA[i] += __shfl_xor_sync(0xffffffffu, sumA[i], 2);
    }
    __syncthreads();
    float* rs = (float*)smem;
    if (wn == 0 && (lane & 3) == 0) {
#pragma unroll
        for (int mt = 0; mt < 4; mt++) {
            rs[wm * 64 + mt * 16 + (lane >> 2)]     = sumA[mt * 2];
            rs[wm * 64 + mt * 16 + 8 + (lane >> 2)] = sumA[mt * 2 + 1];
        }
    }
    __syncthreads();

    const int m0 = mb * 128, n0 = nb * 128;
    const int row0 = m0 + wm * 64 + (lane >> 2);
    const int col0 = n0 + wn * 32 + (lane & 3) * 2;
#pragma unroll
    for (int mt = 0; mt < 4; mt++) {
        const int lr = wm * 64 + mt * 16 + (lane >> 2);
        const float ri0 = 1.0f / rs[lr];
        const float ri1 = 1.0f / rs[lr + 8];
        const int r1 = row0 + mt * 16;
#pragma unroll
        for (int nt = 0; nt < 4; nt++) {
            const int cc = col0 + nt * 8;
            float2 w0, w1;
            w0.x = c[mt][nt][0] * ri0;
            w0.y = c[mt][nt][1] * ri0;
            w1.x = c[mt][nt][2] * ri1;
            w1.y = c[mt][nt][3] * ri1;
            *(float2*)&out[((size_t)b * SEQ + r1) * DIM + cc] = w0;
            *(float2*)&out[((size_t)b * SEQ + r1 + 8) * DIM + cc] = w1;
        }
    }
}

// ---------------- launch ----------------
extern "C" void kernel_launch(void* const* d_in, const int* in_sizes, int n_in,
                              void* d_out, int out_size) {
    const float* x = (const float*)d_in[0];
    float* out = (float*)d_out;

    static bool configured = false;
    if (!configured) {
        cudaFuncSetAttribute(gemm1_kernel,
                             cudaFuncAttributeMaxDynamicSharedMemorySize,
                             SMEM_DYN);
        cudaFuncSetAttribute(gemm2_kernel,
                             cudaFuncAttributeMaxDynamicSharedMemorySize,
                             SMEM_DYN);
        configured = true;
    }

    xhat_kernel<<<BATCH * 16, 256>>>(x);
    xT_kernel<<<dim3(SEQ / 32, DIM / 32, BATCH), dim3(32, 8)>>>(x);
    gemm1_kernel<<<dim3(NPAIR, 1, BATCH), 256, SMEM_DYN>>>();
    gemm2_kernel<<<dim3(DIM / 128, SEQ / 128, BATCH), 256, SMEM_DYN>>>(out);
}

// round 17
// speedup vs baseline: 1.0744x; 1.0744x over previous
#include <cuda_runtime.h>
#include <cuda_fp16.h>
#include <cstdint>

// Cosine self-attention, fp16 mma.sync m16n8k16. Composite of best-measured
// pieces: R13 xhat/gemm1-mainloop (old fragment image, scalar LDS), R15
// gemm2/xT (lane-major image, vector LDS) and R15's verified smem-staged
// gemm1 epilogue writing P in the lane-major image.
// (Resubmission of R15-composite: prior round was an infra failure.)

#define BATCH 16
#define SEQ   2048
#define DIM   512
#define NTILE 16
#define NPAIR 136
#define TILE_U32 2048                 // 128 rows x 32 halves = 8KB
#define TILE_B   8192
#define STAGE_U32 8192                // 2 A-tiles + 2 B-tiles
#define STAGE_B   32768
#define SMEM_DYN  98304               // 3 stages

__device__ __align__(256) uint32_t g_xhA[(size_t)BATCH * 16 * 16 * TILE_U32];
__device__ __align__(256) uint32_t g_xhB[(size_t)BATCH * 16 * 16 * TILE_U32];
__device__ __align__(256) uint32_t g_xT[(size_t)BATCH * 4 * 64 * TILE_U32];
__device__ __align__(256) uint32_t g_P[(size_t)BATCH * 16 * 64 * TILE_U32];

// ---------------- ptx helpers ----------------
__device__ __forceinline__ void mma16(float c[4], const uint32_t a[4],
                                      const uint32_t b[2]) {
    asm volatile(
        "mma.sync.aligned.m16n8k16.row.col.f32.f16.f16.f32 "
        "{%0,%1,%2,%3}, {%4,%5,%6,%7}, {%8,%9}, {%0,%1,%2,%3};"
        : "+f"(c[0]), "+f"(c[1]), "+f"(c[2]), "+f"(c[3])
        : "r"(a[0]), "r"(a[1]), "r"(a[2]), "r"(a[3]), "r"(b[0]), "r"(b[1]));
}
__device__ __forceinline__ uint32_t movmat(uint32_t a) {
    uint32_t d;
    asm("movmatrix.sync.aligned.m8n8.trans.b16 %0, %1;" : "=r"(d) : "r"(a));
    return d;
}
__device__ __forceinline__ void mbar_init(uint32_t mbar, uint32_t cnt) {
    asm volatile("mbarrier.init.shared.b64 [%0], %1;" :: "r"(mbar), "r"(cnt)
                 : "memory");
}
__device__ __forceinline__ void mbar_expect(uint32_t mbar, uint32_t bytes) {
    asm volatile("mbarrier.arrive.expect_tx.shared.b64 _, [%0], %1;"
                 :: "r"(mbar), "r"(bytes) : "memory");
}
__device__ __forceinline__ void mbar_wait(uint32_t mbar, uint32_t parity) {
    asm volatile(
        "{\n\t.reg .pred P1;\n\t"
        "WL_%=:\n\t"
        "mbarrier.try_wait.parity.acquire.cta.shared::cta.b64 P1, [%0], %1, 0x989680;\n\t"
        "@P1 bra.uni WD_%=;\n\t"
        "bra.uni WL_%=;\n\t"
        "WD_%=:\n\t}"
        :: "r"(mbar), "r"(parity) : "memory");
}
__device__ __forceinline__ void bulk_cp(uint32_t dst, const void* src,
                                        uint32_t bytes, uint32_t mbar) {
    asm volatile(
        "cp.async.bulk.shared::cluster.global.mbarrier::complete_tx::bytes "
        "[%0], [%1], %2, [%3];"
        :: "r"(dst), "l"(src), "r"(bytes), "r"(mbar) : "memory");
}
__device__ __forceinline__ void fence_async() {
    asm volatile("fence.proxy.async.shared::cta;" ::: "memory");
}

// ---------- OLD (R13) fragment-image helpers — gemm1 operands ----------
__device__ __forceinline__ int a_img_u4(int r, int q) {
    return (((q >> 1) * 8 + (r >> 4)) * 4 + (q & 1) * 2 + ((r >> 3) & 1)) * 32 +
           (r & 7) * 4;
}
__device__ __forceinline__ int b_img_u4(int n, int q) {
    return (((q >> 1) * 16 + (n >> 3)) * 2 + (q & 1)) * 32 + (n & 7) * 4;
}

// ---------- NEW lane-major image helper — gemm2 B operand (xT) ----------
__device__ __forceinline__ int b_img(int n, int u) {
    const int ks = u >> 3, kp = u & 7;
    return (((ks * 16 + (n >> 3)) * 32) + (n & 7) * 4 + (kp & 3)) * 2 + (kp >> 2);
}

// ---------------- kernel: xhat -> OLD A-image + B-image tiles (R13) --------
__global__ void xhat_kernel(const float* __restrict__ x) {
    const int grow = blockIdx.x * 8 + (threadIdx.x >> 5);
    const int lane = threadIdx.x & 31;
    const float4* src = (const float4*)(x + (size_t)grow * DIM) + lane * 4;
    float4 v[4];
    float ss = 0.f;
#pragma unroll
    for (int i = 0; i < 4; i++) {
        v[i] = src[i];
        ss += v[i].x * v[i].x + v[i].y * v[i].y + v[i].z * v[i].z + v[i].w * v[i].w;
    }
#pragma unroll
    for (int m = 16; m; m >>= 1) ss += __shfl_xor_sync(0xffffffffu, ss, m);
    const float s = 1.0f / sqrtf(ss);
    uint4 U[2];
#pragma unroll
    for (int u = 0; u < 2; u++) {
        __half2 h0 = __floats2half2_rn(v[2 * u].x * s, v[2 * u].y * s);
        __half2 h1 = __floats2half2_rn(v[2 * u].z * s, v[2 * u].w * s);
        __half2 h2 = __floats2half2_rn(v[2 * u + 1].x * s, v[2 * u + 1].y * s);
        __half2 h3 = __floats2half2_rn(v[2 * u + 1].z * s, v[2 * u + 1].w * s);
        U[u].x = *(uint32_t*)&h0; U[u].y = *(uint32_t*)&h1;
        U[u].z = *(uint32_t*)&h2; U[u].w = *(uint32_t*)&h3;
    }
    const int b = grow >> 11, r = grow & 2047, rb = r >> 7, rr = r & 127;
    const int c = lane >> 1;
    uint32_t* tA = g_xhA + ((size_t)((b * 16 + rb) * 16 + c)) * TILE_U32;
    uint32_t* tB = g_xhB + ((size_t)((b * 16 + rb) * 16 + c)) * TILE_U32;
#pragma unroll
    for (int u = 0; u < 2; u++) {
        const int q = (lane & 1) * 2 + u;
        *(uint4*)(tA + a_img_u4(rr, q)) = U[u];
        *(uint4*)(tB + b_img_u4(rr, q)) = U[u];
    }
}

// ---------------- kernel: xT -> NEW B-image tiles (R15) --------------------
__global__ void xT_kernel(const float* __restrict__ x) {
    __shared__ float t[32][33];
    const int b = blockIdx.z, s0 = blockIdx.x * 32, d0 = blockIdx.y * 32;
    const int tx = threadIdx.x, ty = threadIdx.y;
#pragma unroll
    for (int i = 0; i < 4; i++)
        t[ty + 8 * i][tx] = x[((size_t)b * SEQ + s0 + ty + 8 * i) * DIM + d0 + tx];
    __syncthreads();
    const int kc = s0 >> 5;
    const int nb = d0 >> 7;
    const int n  = (d0 & 127) + tx;
    uint32_t* tile = g_xT + ((size_t)((b * 4 + nb) * 64 + kc)) * TILE_U32;
#pragma unroll
    for (int i = 0; i < 2; i++) {
        const int u = ty + 8 * i;
        __half2 hv = __floats2half2_rn(t[2 * u][tx], t[2 * u + 1][tx]);
        tile[b_img(n, u)] = *(uint32_t*)&hv;
    }
}

// ------------- compute chunks: OLD (scalar LDS) and NEW (vector LDS) -------
__device__ __forceinline__ void compute_chunk_old(const uint32_t* Abuf,
                                                  const uint32_t* Bbuf,
                                                  float c[4][4][4], int wm,
                                                  int wn, int lane) {
#pragma unroll
    for (int ks = 0; ks < 2; ks++) {
        uint32_t a[4][4], b[4][2];
#pragma unroll
        for (int mt = 0; mt < 4; mt++) {
            const uint32_t* p = Abuf + ((ks * 8 + wm * 4 + mt) * 4) * 32 + lane;
#pragma unroll
            for (int j = 0; j < 4; j++) a[mt][j] = p[j * 32];
        }
#pragma unroll
        for (int nt = 0; nt < 4; nt++) {
            const uint32_t* p = Bbuf + ((ks * 16 + wn * 4 + nt) * 2) * 32 + lane;
#pragma unroll
            for (int j = 0; j < 2; j++) b[nt][j] = p[j * 32];
        }
#pragma unroll
        for (int mt = 0; mt < 4; mt++)
#pragma unroll
            for (int nt = 0; nt < 4; nt++)
                mma16(c[mt][nt], a[mt], b[nt]);
    }
}

template <bool SUMROWS>
__device__ __forceinline__ void compute_chunk_new(const uint32_t* Abuf,
                                                  const uint32_t* Bbuf,
                                                  float c[4][4][4], int wm,
                                                  int wn, int lane,
                                                  float* sumA) {
#pragma unroll
    for (int ks = 0; ks < 2; ks++) {
        uint32_t a[4][4], b[4][2];
#pragma unroll
        for (int mt = 0; mt < 4; mt++) {
            uint4 v = *((const uint4*)Abuf + ((ks * 8 + wm * 4 + mt) * 32 + lane));
            a[mt][0] = v.x; a[mt][1] = v.y; a[mt][2] = v.z; a[mt][3] = v.w;
        }
#pragma unroll
        for (int nt = 0; nt < 4; nt++) {
            uint2 v = *((const uint2*)Bbuf + ((ks * 16 + wn * 4 + nt) * 32 + lane));
            b[nt][0] = v.x; b[nt][1] = v.y;
        }
        if (SUMROWS && wn == 0) {
#pragma unroll
            for (int mt = 0; mt < 4; mt++) {
                float2 f0 = __half22float2(*(__half2*)&a[mt][0]);
                float2 f2 = __half22float2(*(__half2*)&a[mt][2]);
                sumA[mt * 2] += (f0.x + f0.y) + (f2.x + f2.y);
                float2 f1 = __half22float2(*(__half2*)&a[mt][1]);
                float2 f3 = __half22float2(*(__half2*)&a[mt][3]);
                sumA[mt * 2 + 1] += (f1.x + f1.y) + (f3.x + f3.y);
            }
        }
#pragma unroll
        for (int mt = 0; mt < 4; mt++)
#pragma unroll
            for (int nt = 0; nt < 4; nt++)
                mma16(c[mt][nt], a[mt], b[nt]);
    }
}

// Chunk = 64 K-halves = 2 consecutive 8KB tiles per operand.
template <bool NEWIMG, bool SUMROWS>
__device__ __forceinline__ void gemm_main(const char* Abase, const char* Bbase,
                                          int T, float c[4][4][4],
                                          uint32_t* smem, uint32_t smem_u32,
                                          uint32_t mbar_u32, int tid, int wm,
                                          int wn, int lane, float* sumA) {
    uint32_t ph0 = 0, ph1 = 0, ph2 = 0;
    auto issue = [&](int t) {
        if (tid == 0) {
            const int s = t % 3;
            const uint32_t mb = mbar_u32 + s * 8;
            mbar_expect(mb, STAGE_B);
            bulk_cp(smem_u32 + s * STAGE_B, Abase + (size_t)t * 2 * TILE_B,
                    2 * TILE_B, mb);
            bulk_cp(smem_u32 + s * STAGE_B + 2 * TILE_B,
                    Bbase + (size_t)t * 2 * TILE_B, 2 * TILE_B, mb);
        }
    };
    issue(0);
    if (T > 1) issue(1);
    for (int t = 0; t < T; t++) {
        const int s = t % 3;
        const uint32_t mb = mbar_u32 + s * 8;
        if (s == 0)      { mbar_wait(mb, ph0); ph0 ^= 1; }
        else if (s == 1) { mbar_wait(mb, ph1); ph1 ^= 1; }
        else             { mbar_wait(mb, ph2); ph2 ^= 1; }
        __syncthreads();
        if (t + 2 < T) issue(t + 2);
#pragma unroll
        for (int u = 0; u < 2; u++) {
            const uint32_t* Abuf = smem + s * STAGE_U32 + u * TILE_U32;
            const uint32_t* Bbuf = smem + s * STAGE_U32 + 2 * TILE_U32 +
                                   u * TILE_U32;
            if (NEWIMG)
                compute_chunk_new<SUMROWS>(Abuf, Bbuf, c, wm, wn, lane, sumA);
            else
                compute_chunk_old(Abuf, Bbuf, c, wm, wn, lane);
        }
    }
}

// ------- kernel: GEMM1 (symmetric)  P = half(exp(xhat xhat^T - 1)) ---------
// R13 mainloop (old image); R15 staged epilogue writing lane-major P image.
__global__ __launch_bounds__(256, 2) void gemm1_kernel() {
    extern __shared__ __align__(128) uint32_t smem[];
    __shared__ __align__(8) unsigned long long mbars[3];
    const uint32_t smem_u32 = (uint32_t)__cvta_generic_to_shared(smem);
    const uint32_t mbar_u32 = (uint32_t)__cvta_generic_to_shared(mbars);
    const int b = blockIdx.z;
    const int idx = blockIdx.x;
    int ti = (int)(NTILE + 0.5f -
                   sqrtf((NTILE + 0.5f) * (NTILE + 0.5f) - 2.0f * idx - 0.25f));
    while (ti * NTILE - ti * (ti - 1) / 2 > idx) ti--;
    while ((ti + 1) * NTILE - (ti + 1) * ti / 2 <= idx) ti++;
    const int tj = ti + (idx - (ti * NTILE - ti * (ti - 1) / 2));

    const int tid = threadIdx.x, wid = tid >> 5, lane = tid & 31;
    const int wm = wid >> 2, wn = wid & 3;

    if (tid == 0) {
#pragma unroll
        for (int s = 0; s < 3; s++) mbar_init(mbar_u32 + s * 8, 1);
        fence_async();
    }
    __syncthreads();

    const char* Abase =
        (const char*)(g_xhA + ((size_t)((b * 16 + ti) * 16)) * TILE_U32);
    const char* Bbase =
        (const char*)(g_xhB + ((size_t)((b * 16 + tj) * 16)) * TILE_U32);

    float c[4][4][4];
#pragma unroll
    for (int i = 0; i < 4; i++)
#pragma unroll
        for (int j = 0; j < 4; j++)
#pragma unroll
            for (int k = 0; k < 4; k++) c[i][j][k] = 0.f;
    float dummy[8];

    gemm_main<false, false>(Abase, Bbase, DIM / 64, c, smem, smem_u32, mbar_u32,
                            tid, wm, wn, lane, dummy);

    // --- epilogue: stage direct + mirror lane-major images, flush coalesced -
    const bool mirror = (ti != tj);
    __syncthreads();                    // pipeline smem now dead
    uint32_t* sD = smem;                // 4 tiles (q = wn)
    uint32_t* sM = smem + 8192;         // 4 tiles (q = wm*2+(mt>>1))
#pragma unroll
    for (int mt = 0; mt < 4; mt++) {
#pragma unroll
        for (int nt = 0; nt < 4; nt++) {
            __half2 h0 = __floats2half2_rn(__expf(c[mt][nt][0] - 1.0f),
                                           __expf(c[mt][nt][1] - 1.0f));
            __half2 h1 = __floats2half2_rn(__expf(c[mt][nt][2] - 1.0f),
                                           __expf(c[mt][nt][3] - 1.0f));
            const int ia = wn * TILE_U32 +
                           (((nt >> 1) * 8 + wm * 4 + mt) * 32 + lane) * 4 +
                           (nt & 1) * 2;
            sD[ia]     = *(uint32_t*)&h0;
            sD[ia + 1] = *(uint32_t*)&h1;
            if (mirror) {
                uint32_t t0 = movmat(*(uint32_t*)&h0);
                uint32_t t1 = movmat(*(uint32_t*)&h1);
                const int im = (wm * 2 + (mt >> 1)) * TILE_U32 +
                               (((mt & 1) * 8 + wn * 2 + (nt >> 1)) * 32 + lane)
                                   * 4 + (nt & 1);
                sM[im]     = t0;
                sM[im + 2] = t1;
            }
        }
    }
    __syncthreads();
    uint4* dD = (uint4*)(g_P + ((size_t)((b * 16 + ti) * 64 + tj * 4)) * TILE_U32);
#pragma unroll
    for (int i = 0; i < 8; i++)
        dD[tid + i * 256] = ((const uint4*)sD)[tid + i * 256];
    if (mirror) {
        uint4* dM =
            (uint4*)(g_P + ((size_t)((b * 16 + tj) * 64 + ti * 4)) * TILE_U32);
#pragma unroll
        for (int i = 0; i < 8; i++)
            dM[tid + i * 256] = ((const uint4*)sM)[tid + i * 256];
    }
}

// ------- kernel: GEMM2  out = (P @ x) / rowsum(P)  (R15 verbatim) ----------
__global__ __launch_bounds__(256, 2) void gemm2_kernel(float* __restrict__ out) {
    extern __shared__ __align__(128) uint32_t smem[];
    __shared__ __align__(8) unsigned long long mbars[3];
    const uint32_t smem_u32 = (uint32_t)__cvta_generic_to_shared(smem);
    const uint32_t mbar_u32 = (uint32_t)__cvta_generic_to_shared(mbars);
    const int b = blockIdx.z, mb = blockIdx.y, nb = blockIdx.x;
    const int tid = threadIdx.x, wid = tid >> 5, lane = tid & 31;
    const int wm = wid >> 2, wn = wid & 3;

    if (tid == 0) {
#pragma unroll
        for (int s = 0; s < 3; s++) mbar_init(mbar_u32 + s * 8, 1);
        fence_async();
    }
    __syncthreads();

    const char* Abase =
        (const char*)(g_P + ((size_t)((b * 16 + mb) * 64)) * TILE_U32);
    const char* Bbase =
        (const char*)(g_xT + ((size_t)((b * 4 + nb) * 64)) * TILE_U32);

    float c[4][4][4];
#pragma unroll
    for (int i = 0; i < 4; i++)
#pragma unroll
        for (int j = 0; j < 4; j++)
#pragma unroll
            for (int k = 0; k < 4; k++) c[i][j][k] = 0.f;
    float sumA[8];
#pragma unroll
    for (int i = 0; i < 8; i++) sumA[i] = 0.f;

    gemm_main<true, true>(Abase, Bbase, SEQ / 64, c, smem, smem_u32, mbar_u32,
                          tid, wm, wn, lane, sumA);

#pragma unroll
    for (int i = 0; i < 8; i++) {
        sumA[i] += __shfl_xor_sync(0xffffffffu, sumA[i], 1);
        sumA[i] += __shfl_xor_sync(0xffffffffu, sumA[i], 2);
    }
    __syncthreads();
    float* rs = (float*)smem;
    if (wn == 0 && (lane & 3) == 0) {
#pragma unroll
        for (int mt = 0; mt < 4; mt++) {
            rs[wm * 64 + mt * 16 + (lane >> 2)]     = sumA[mt * 2];
            rs[wm * 64 + mt * 16 + 8 + (lane >> 2)] = sumA[mt * 2 + 1];
        }
    }
    __syncthreads();

    const int m0 = mb * 128, n0 = nb * 128;
    const int row0 = m0 + wm * 64 + (lane >> 2);
    const int col0 = n0 + wn * 32 + (lane & 3) * 2;
#pragma unroll
    for (int mt = 0; mt < 4; mt++) {
        const int lr = wm * 64 + mt * 16 + (lane >> 2);
        const float ri0 = 1.0f / rs[lr];
        const float ri1 = 1.0f / rs[lr + 8];
        const int r1 = row0 + mt * 16;
#pragma unroll
        for (int nt = 0; nt < 4; nt++) {
            const int cc = col0 + nt * 8;
            float2 w0, w1;
            w0.x = c[mt][nt][0] * ri0;
            w0.y = c[mt][nt][1] * ri0;
            w1.x = c[mt][nt][2] * ri1;
            w1.y = c[mt][nt][3] * ri1;
            *(float2*)&out[((size_t)b * SEQ + r1) * DIM + cc] = w0;
            *(float2*)&out[((size_t)b * SEQ + r1 + 8) * DIM + cc] = w1;
        }
    }
}

// ---------------- launch ----------------
extern "C" void kernel_launch(void* const* d_in, const int* in_sizes, int n_in,
                              void* d_out, int out_size) {
    const float* x = (const float*)d_in[0];
    float* out = (float*)d_out;

    static bool configured = false;
    if (!configured) {
        cudaFuncSetAttribute(gemm1_kernel,
                             cudaFuncAttributeMaxDynamicSharedMemorySize,
                             SMEM_DYN);
        cudaFuncSetAttribute(gemm2_kernel,
                             cudaFuncAttributeMaxDynamicSharedMemorySize,
                             SMEM_DYN);
        configured = true;
    }

    xhat_kernel<<<BATCH * SEQ / 8, 256>>>(x);
    xT_kernel<<<dim3(SEQ / 32, DIM / 32, BATCH), dim3(32, 8)>>>(x);
    gemm1_kernel<<<dim3(NPAIR, 1, BATCH), 256, SMEM_DYN>>>();
    gemm2_kernel<<<dim3(DIM / 128, SEQ / 128, BATCH), 256, SMEM_DYN>>>(out);
}